// round 9
// baseline (speedup 1.0000x reference)
#include <cuda_runtime.h>
#include <cuda_fp16.h>
#include <cstdint>

// ---------------------------------------------------------------------------
// MGDCF diffusion: h_{t+1} = BETA * A_norm h_t + ALPHA * h0, K=4 steps.
// Round 9: R8 base +
//   (a) __launch_bounds__(256, 6) on spmm kernels (occupancy 52% -> ~75%),
//   (b) degree-matched gather slots: 8-slot unrolled path for user rows
//       (deg ~ Poisson(5)), 16-slot path for item rows (deg ~ Poisson(10)).
// Step 1 keeps mapping-B coalesced fp32 gathers + folded anchor.
// ---------------------------------------------------------------------------

#define NUSERS 200000
#define NITEMS 100000
#define NN     300000              // total nodes (div by 4 -> exact tiling)
#define NE     1000000             // user-item pairs
#define DD     64                  // feature dim

static constexpr float ALPHA_C = 0.1f;
static constexpr float BETA_C  = 0.9f;
static constexpr double GAMMA_D =
    (0.9 * 0.9 * 0.9 * 0.9) + 0.1 * (1.0 + 0.9 + 0.81 + 0.729);   // = 1.0
static constexpr float INV_GAMMA = (float)(1.0 / GAMMA_D);

// ------------------------- device scratch (static) -------------------------
__device__ __half g_hh[2][(size_t)NN * DD];  // ping-pong fp16 h buffers (76.8 MB)
__device__ int    g_cnt[NN];                 // real in-degree (excl. self loop)
__device__ float  g_norm[NN];                // (deg incl. self)^-1/2
__device__ int2   g_rowinfo[NN];             // (segment start, real in-degree)
__device__ int    g_cursor[NN];              // fill cursors
__device__ uint2  g_edge[2 * NE];            // (src, norm[src] bits), 16 MB
__device__ int    g_alloc;                   // global segment allocator

// ------------------------------ build kernels ------------------------------

__global__ void count_kernel(const int* __restrict__ uidx,
                             const int* __restrict__ iidx) {
    int e = blockIdx.x * blockDim.x + threadIdx.x;
    if (e >= NE) return;
    int u  = uidx[e];
    int it = iidx[e] + NUSERS;
    atomicAdd(&g_cnt[u], 1);
    atomicAdd(&g_cnt[it], 1);
}

__global__ void alloc_kernel() {
    int v    = blockIdx.x * blockDim.x + threadIdx.x;
    int lane = threadIdx.x & 31;
    int c = 0;
    if (v < NN) {
        c = g_cnt[v];
        g_norm[v] = rsqrtf((float)(c + 1));
    }
    int inc = c;
    #pragma unroll
    for (int o = 1; o < 32; o <<= 1) {
        int t = __shfl_up_sync(0xFFFFFFFFu, inc, o);
        if (lane >= o) inc += t;
    }
    int total = __shfl_sync(0xFFFFFFFFu, inc, 31);
    int base = 0;
    if (lane == 31) base = atomicAdd(&g_alloc, total);
    base = __shfl_sync(0xFFFFFFFFu, base, 31);
    if (v < NN) {
        int st = base + inc - c;
        g_rowinfo[v] = make_int2(st, c);
        g_cursor[v]  = st;
    }
}

__global__ void fill_kernel(const int* __restrict__ uidx,
                            const int* __restrict__ iidx) {
    int e = blockIdx.x * blockDim.x + threadIdx.x;
    if (e >= NE) return;
    int u  = uidx[e];
    int it = iidx[e] + NUSERS;
    float nu = g_norm[u];
    float ni = g_norm[it];
    int p0 = atomicAdd(&g_cursor[it], 1);
    g_edge[p0] = make_uint2((unsigned)u, __float_as_uint(nu));
    int p1 = atomicAdd(&g_cursor[u], 1);
    g_edge[p1] = make_uint2((unsigned)it, __float_as_uint(ni));
}

// ----------------------- 8-wide row load/store helpers ----------------------
// Mapping A (fp16 rows): lane `sub` owns columns [sub*8, sub*8+8).

__device__ __forceinline__ void loadRow8(const float* __restrict__ h,
                                         unsigned row, int sub, float v[8]) {
    const float4* p = (const float4*)(h + (size_t)row * DD) + sub * 2;
    float4 a = p[0];
    float4 b = p[1];
    v[0]=a.x; v[1]=a.y; v[2]=a.z; v[3]=a.w;
    v[4]=b.x; v[5]=b.y; v[6]=b.z; v[7]=b.w;
}
__device__ __forceinline__ void loadRow8(const __half* __restrict__ h,
                                         unsigned row, int sub, float v[8]) {
    uint4 r = ((const uint4*)(h + (size_t)row * DD))[sub];
    float2 f0 = __half22float2(*(__half2*)&r.x);
    float2 f1 = __half22float2(*(__half2*)&r.y);
    float2 f2 = __half22float2(*(__half2*)&r.z);
    float2 f3 = __half22float2(*(__half2*)&r.w);
    v[0]=f0.x; v[1]=f0.y; v[2]=f1.x; v[3]=f1.y;
    v[4]=f2.x; v[5]=f2.y; v[6]=f3.x; v[7]=f3.y;
}
__device__ __forceinline__ void storeRow8(float* __restrict__ h,
                                          unsigned row, int sub, const float v[8]) {
    float4* p = (float4*)(h + (size_t)row * DD) + sub * 2;
    p[0] = make_float4(v[0], v[1], v[2], v[3]);
    p[1] = make_float4(v[4], v[5], v[6], v[7]);
}
__device__ __forceinline__ void storeRow8(__half* __restrict__ h,
                                          unsigned row, int sub, const float v[8]) {
    __half2 h0 = __floats2half2_rn(v[0], v[1]);
    __half2 h1 = __floats2half2_rn(v[2], v[3]);
    __half2 h2 = __floats2half2_rn(v[4], v[5]);
    __half2 h3 = __floats2half2_rn(v[6], v[7]);
    uint4 r;
    r.x = *(unsigned*)&h0;  r.y = *(unsigned*)&h1;
    r.z = *(unsigned*)&h2;  r.w = *(unsigned*)&h3;
    ((uint4*)(h + (size_t)row * DD))[sub] = r;
}

// Mapping B (fp32 rows, coalesced): lane `sub` owns columns
// {4*sub..+4} and {32+4*sub..+4}; loads are p[sub], p[sub+8] (128B coalesced).
__device__ __forceinline__ void loadRowB(const float* __restrict__ h,
                                         unsigned row, int sub, float v[8]) {
    const float4* p = (const float4*)(h + (size_t)row * DD);
    float4 a = p[sub];
    float4 b = p[sub + 8];
    v[0]=a.x; v[1]=a.y; v[2]=a.z; v[3]=a.w;
    v[4]=b.x; v[5]=b.y; v[6]=b.z; v[7]=b.w;
}
__device__ __forceinline__ void storeRowB(__half* __restrict__ h,
                                          unsigned row, int sub, const float v[8]) {
    __half2 q0 = __floats2half2_rn(v[0], v[1]);
    __half2 q1 = __floats2half2_rn(v[2], v[3]);
    __half2 q2 = __floats2half2_rn(v[4], v[5]);
    __half2 q3 = __floats2half2_rn(v[6], v[7]);
    uint2 r0, r1;
    r0.x = *(unsigned*)&q0;  r0.y = *(unsigned*)&q1;   // cols 4*sub..+4
    r1.x = *(unsigned*)&q2;  r1.y = *(unsigned*)&q3;   // cols 32+4*sub..+4
    uint2* p = (uint2*)(h + (size_t)row * DD);
    p[sub]     = r0;
    p[sub + 8] = r1;
}

// --------------------------- SpMM kernel (fp16 src) -------------------------
// Four rows per warp, 8 lanes/row, lane owns 8 columns (mapping A).
// User rows (deg~5): 8 unrolled slots + scalar tail. Item rows (deg~10):
// 16 unrolled slots + scalar tail. Row type is warp-uniform.
template <typename DstT>
__global__ void __launch_bounds__(256, 6)
spmm_kernel(const __half* __restrict__ hsrc, DstT* __restrict__ hdst,
            const float* __restrict__ x, float fs) {
    const int lane = threadIdx.x & 31;
    const int sub  = lane & 7;
    const int team = lane >> 3;
    const int warp = blockIdx.x * (blockDim.x >> 5) + (threadIdx.x >> 5);
    const unsigned row = warp * 4 + team;   // exact tiling: never >= NN

    const int2 info = g_rowinfo[row];
    const int  st   = info.x;
    const int  len  = info.y;
    const float nv  = rsqrtf((float)(len + 1));

    float acc[8];
    #pragma unroll
    for (int k = 0; k < 8; k++) acc[k] = 0.f;

    if (row < NUSERS) {
        // ---- user rows: 8 unrolled slots ----
        const int n8 = (len < 8) ? len : 8;
        uint2 e0 = make_uint2(0u, 0u);
        if (sub < n8) e0 = g_edge[st + sub];
        #pragma unroll
        for (int j = 0; j < 8; j++) {
            unsigned sx = __shfl_sync(0xFFFFFFFFu, e0.x, j, 8);
            unsigned wb = __shfl_sync(0xFFFFFFFFu, e0.y, j, 8);
            if (j < n8) {
                float w = __uint_as_float(wb);
                float v[8];
                loadRow8(hsrc, sx, sub, v);
                #pragma unroll
                for (int k = 0; k < 8; k++) acc[k] = fmaf(w, v[k], acc[k]);
            }
        }
        for (int j = 8; j < len; j++) {               // deg > 8 tail (~7%)
            uint2 e2 = g_edge[st + j];
            float w = __uint_as_float(e2.y);
            float v[8];
            loadRow8(hsrc, e2.x, sub, v);
            #pragma unroll
            for (int k = 0; k < 8; k++) acc[k] = fmaf(w, v[k], acc[k]);
        }
    } else {
        // ---- item rows: 16 unrolled slots ----
        const int n16 = (len < 16) ? len : 16;
        uint2 e0 = make_uint2(0u, 0u);
        uint2 e1 = make_uint2(0u, 0u);
        if (sub < n16)     e0 = g_edge[st + sub];
        if (sub + 8 < n16) e1 = g_edge[st + sub + 8];
        #pragma unroll
        for (int j = 0; j < 16; j++) {
            unsigned sx = __shfl_sync(0xFFFFFFFFu, (j < 8) ? e0.x : e1.x, j & 7, 8);
            unsigned wb = __shfl_sync(0xFFFFFFFFu, (j < 8) ? e0.y : e1.y, j & 7, 8);
            if (j < n16) {
                float w = __uint_as_float(wb);
                float v[8];
                loadRow8(hsrc, sx, sub, v);
                #pragma unroll
                for (int k = 0; k < 8; k++) acc[k] = fmaf(w, v[k], acc[k]);
            }
        }
        for (int j = 16; j < len; j++) {              // deg > 16 tail (rare)
            uint2 e2 = g_edge[st + j];
            float w = __uint_as_float(e2.y);
            float v[8];
            loadRow8(hsrc, e2.x, sub, v);
            #pragma unroll
            for (int k = 0; k < 8; k++) acc[k] = fmaf(w, v[k], acc[k]);
        }
    }

    float sh[8], x0[8];
    loadRow8(hsrc, row, sub, sh);
    loadRow8(x,    row, sub, x0);

    const float cn = BETA_C * nv;
    const float cs = BETA_C * nv * nv;

    float r[8];
    #pragma unroll
    for (int k = 0; k < 8; k++)
        r[k] = fmaf(cn, acc[k], fmaf(cs, sh[k], ALPHA_C * x0[k])) * fs;

    storeRow8(hdst, row, sub, r);
}

// ------------------------ step-1 kernel (fp32 src = x) ----------------------
// Mapping B for coalesced fp32 gathers; anchor folded into self term.
// Same user/item slot split. storeRowB writes canonical layout.
__global__ void __launch_bounds__(256, 6)
spmm_step1_kernel(const float* __restrict__ x, __half* __restrict__ hdst) {
    const int lane = threadIdx.x & 31;
    const int sub  = lane & 7;
    const int team = lane >> 3;
    const int warp = blockIdx.x * (blockDim.x >> 5) + (threadIdx.x >> 5);
    const unsigned row = warp * 4 + team;

    const int2 info = g_rowinfo[row];
    const int  st   = info.x;
    const int  len  = info.y;
    const float nv  = rsqrtf((float)(len + 1));

    float acc[8];
    #pragma unroll
    for (int k = 0; k < 8; k++) acc[k] = 0.f;

    if (row < NUSERS) {
        const int n8 = (len < 8) ? len : 8;
        uint2 e0 = make_uint2(0u, 0u);
        if (sub < n8) e0 = g_edge[st + sub];
        #pragma unroll
        for (int j = 0; j < 8; j++) {
            unsigned sx = __shfl_sync(0xFFFFFFFFu, e0.x, j, 8);
            unsigned wb = __shfl_sync(0xFFFFFFFFu, e0.y, j, 8);
            if (j < n8) {
                float w = __uint_as_float(wb);
                float v[8];
                loadRowB(x, sx, sub, v);
                #pragma unroll
                for (int k = 0; k < 8; k++) acc[k] = fmaf(w, v[k], acc[k]);
            }
        }
        for (int j = 8; j < len; j++) {
            uint2 e2 = g_edge[st + j];
            float w = __uint_as_float(e2.y);
            float v[8];
            loadRowB(x, e2.x, sub, v);
            #pragma unroll
            for (int k = 0; k < 8; k++) acc[k] = fmaf(w, v[k], acc[k]);
        }
    } else {
        const int n16 = (len < 16) ? len : 16;
        uint2 e0 = make_uint2(0u, 0u);
        uint2 e1 = make_uint2(0u, 0u);
        if (sub < n16)     e0 = g_edge[st + sub];
        if (sub + 8 < n16) e1 = g_edge[st + sub + 8];
        #pragma unroll
        for (int j = 0; j < 16; j++) {
            unsigned sx = __shfl_sync(0xFFFFFFFFu, (j < 8) ? e0.x : e1.x, j & 7, 8);
            unsigned wb = __shfl_sync(0xFFFFFFFFu, (j < 8) ? e0.y : e1.y, j & 7, 8);
            if (j < n16) {
                float w = __uint_as_float(wb);
                float v[8];
                loadRowB(x, sx, sub, v);
                #pragma unroll
                for (int k = 0; k < 8; k++) acc[k] = fmaf(w, v[k], acc[k]);
            }
        }
        for (int j = 16; j < len; j++) {
            uint2 e2 = g_edge[st + j];
            float w = __uint_as_float(e2.y);
            float v[8];
            loadRowB(x, e2.x, sub, v);
            #pragma unroll
            for (int k = 0; k < 8; k++) acc[k] = fmaf(w, v[k], acc[k]);
        }
    }

    float sh[8];
    loadRowB(x, row, sub, sh);

    const float cn = BETA_C * nv;
    const float ca = BETA_C * nv * nv + ALPHA_C;    // folded self + anchor

    float r[8];
    #pragma unroll
    for (int k = 0; k < 8; k++)
        r[k] = fmaf(cn, acc[k], ca * sh[k]);

    storeRowB(hdst, row, sub, r);
}

// --------------------------------- launch ----------------------------------
extern "C" void kernel_launch(void* const* d_in, const int* in_sizes, int n_in,
                              void* d_out, int out_size) {
    const float* x    = (const float*)d_in[0];
    const int*   uidx = (const int*)  d_in[1];
    const int*   iidx = (const int*)  d_in[2];
    float*       out  = (float*)d_out;

    const int T = 256;

    void* p_cnt   = nullptr; cudaGetSymbolAddress(&p_cnt,   g_cnt);
    void* p_alloc = nullptr; cudaGetSymbolAddress(&p_alloc, g_alloc);
    void* p_hh    = nullptr; cudaGetSymbolAddress(&p_hh,    g_hh);
    __half* h0 = (__half*)p_hh;
    __half* h1 = h0 + (size_t)NN * DD;

    // ---- CSR build ----
    cudaMemsetAsync(p_cnt,   0, sizeof(int) * NN);
    cudaMemsetAsync(p_alloc, 0, sizeof(int));
    count_kernel<<<(NE + T - 1) / T, T>>>(uidx, iidx);
    alloc_kernel<<<(NN + T - 1) / T, T>>>();
    fill_kernel <<<(NE + T - 1) / T, T>>>(uidx, iidx);

    // ---- K = 4 diffusion steps ----
    const int rows_per_blk = (T / 32) * 4;            // 32 rows / block
    const int spmm_blocks  = (NN + rows_per_blk - 1) / rows_per_blk;

    spmm_step1_kernel<<<spmm_blocks, T>>>(x, h0);
    spmm_kernel<__half><<<spmm_blocks, T>>>(h0, h1, x, 1.0f);
    spmm_kernel<__half><<<spmm_blocks, T>>>(h1, h0, x, 1.0f);
    spmm_kernel<float ><<<spmm_blocks, T>>>(h0, out, x, INV_GAMMA);
}

// round 10
// speedup vs baseline: 1.0076x; 1.0076x over previous
#include <cuda_runtime.h>
#include <cuda_fp16.h>
#include <cstdint>

// ---------------------------------------------------------------------------
// MGDCF diffusion: h_{t+1} = BETA * A_norm h_t + ALPHA * h0, K=4 steps.
// Round 9: R8 base +
//   (a) __launch_bounds__(256, 6) on spmm kernels (occupancy 52% -> ~75%),
//   (b) degree-matched gather slots: 8-slot unrolled path for user rows
//       (deg ~ Poisson(5)), 16-slot path for item rows (deg ~ Poisson(10)).
// Step 1 keeps mapping-B coalesced fp32 gathers + folded anchor.
// ---------------------------------------------------------------------------

#define NUSERS 200000
#define NITEMS 100000
#define NN     300000              // total nodes (div by 4 -> exact tiling)
#define NE     1000000             // user-item pairs
#define DD     64                  // feature dim

static constexpr float ALPHA_C = 0.1f;
static constexpr float BETA_C  = 0.9f;
static constexpr double GAMMA_D =
    (0.9 * 0.9 * 0.9 * 0.9) + 0.1 * (1.0 + 0.9 + 0.81 + 0.729);   // = 1.0
static constexpr float INV_GAMMA = (float)(1.0 / GAMMA_D);

// ------------------------- device scratch (static) -------------------------
__device__ __half g_hh[2][(size_t)NN * DD];  // ping-pong fp16 h buffers (76.8 MB)
__device__ int    g_cnt[NN];                 // real in-degree (excl. self loop)
__device__ float  g_norm[NN];                // (deg incl. self)^-1/2
__device__ int2   g_rowinfo[NN];             // (segment start, real in-degree)
__device__ int    g_cursor[NN];              // fill cursors
__device__ uint2  g_edge[2 * NE];            // (src, norm[src] bits), 16 MB
__device__ int    g_alloc;                   // global segment allocator

// ------------------------------ build kernels ------------------------------

__global__ void count_kernel(const int* __restrict__ uidx,
                             const int* __restrict__ iidx) {
    int e = blockIdx.x * blockDim.x + threadIdx.x;
    if (e >= NE) return;
    int u  = uidx[e];
    int it = iidx[e] + NUSERS;
    atomicAdd(&g_cnt[u], 1);
    atomicAdd(&g_cnt[it], 1);
}

__global__ void alloc_kernel() {
    int v    = blockIdx.x * blockDim.x + threadIdx.x;
    int lane = threadIdx.x & 31;
    int c = 0;
    if (v < NN) {
        c = g_cnt[v];
        g_norm[v] = rsqrtf((float)(c + 1));
    }
    int inc = c;
    #pragma unroll
    for (int o = 1; o < 32; o <<= 1) {
        int t = __shfl_up_sync(0xFFFFFFFFu, inc, o);
        if (lane >= o) inc += t;
    }
    int total = __shfl_sync(0xFFFFFFFFu, inc, 31);
    int base = 0;
    if (lane == 31) base = atomicAdd(&g_alloc, total);
    base = __shfl_sync(0xFFFFFFFFu, base, 31);
    if (v < NN) {
        int st = base + inc - c;
        g_rowinfo[v] = make_int2(st, c);
        g_cursor[v]  = st;
    }
}

__global__ void fill_kernel(const int* __restrict__ uidx,
                            const int* __restrict__ iidx) {
    int e = blockIdx.x * blockDim.x + threadIdx.x;
    if (e >= NE) return;
    int u  = uidx[e];
    int it = iidx[e] + NUSERS;
    float nu = g_norm[u];
    float ni = g_norm[it];
    int p0 = atomicAdd(&g_cursor[it], 1);
    g_edge[p0] = make_uint2((unsigned)u, __float_as_uint(nu));
    int p1 = atomicAdd(&g_cursor[u], 1);
    g_edge[p1] = make_uint2((unsigned)it, __float_as_uint(ni));
}

// ----------------------- 8-wide row load/store helpers ----------------------
// Mapping A (fp16 rows): lane `sub` owns columns [sub*8, sub*8+8).

__device__ __forceinline__ void loadRow8(const float* __restrict__ h,
                                         unsigned row, int sub, float v[8]) {
    const float4* p = (const float4*)(h + (size_t)row * DD) + sub * 2;
    float4 a = p[0];
    float4 b = p[1];
    v[0]=a.x; v[1]=a.y; v[2]=a.z; v[3]=a.w;
    v[4]=b.x; v[5]=b.y; v[6]=b.z; v[7]=b.w;
}
__device__ __forceinline__ void loadRow8(const __half* __restrict__ h,
                                         unsigned row, int sub, float v[8]) {
    uint4 r = ((const uint4*)(h + (size_t)row * DD))[sub];
    float2 f0 = __half22float2(*(__half2*)&r.x);
    float2 f1 = __half22float2(*(__half2*)&r.y);
    float2 f2 = __half22float2(*(__half2*)&r.z);
    float2 f3 = __half22float2(*(__half2*)&r.w);
    v[0]=f0.x; v[1]=f0.y; v[2]=f1.x; v[3]=f1.y;
    v[4]=f2.x; v[5]=f2.y; v[6]=f3.x; v[7]=f3.y;
}
__device__ __forceinline__ void storeRow8(float* __restrict__ h,
                                          unsigned row, int sub, const float v[8]) {
    float4* p = (float4*)(h + (size_t)row * DD) + sub * 2;
    p[0] = make_float4(v[0], v[1], v[2], v[3]);
    p[1] = make_float4(v[4], v[5], v[6], v[7]);
}
__device__ __forceinline__ void storeRow8(__half* __restrict__ h,
                                          unsigned row, int sub, const float v[8]) {
    __half2 h0 = __floats2half2_rn(v[0], v[1]);
    __half2 h1 = __floats2half2_rn(v[2], v[3]);
    __half2 h2 = __floats2half2_rn(v[4], v[5]);
    __half2 h3 = __floats2half2_rn(v[6], v[7]);
    uint4 r;
    r.x = *(unsigned*)&h0;  r.y = *(unsigned*)&h1;
    r.z = *(unsigned*)&h2;  r.w = *(unsigned*)&h3;
    ((uint4*)(h + (size_t)row * DD))[sub] = r;
}

// Mapping B (fp32 rows, coalesced): lane `sub` owns columns
// {4*sub..+4} and {32+4*sub..+4}; loads are p[sub], p[sub+8] (128B coalesced).
__device__ __forceinline__ void loadRowB(const float* __restrict__ h,
                                         unsigned row, int sub, float v[8]) {
    const float4* p = (const float4*)(h + (size_t)row * DD);
    float4 a = p[sub];
    float4 b = p[sub + 8];
    v[0]=a.x; v[1]=a.y; v[2]=a.z; v[3]=a.w;
    v[4]=b.x; v[5]=b.y; v[6]=b.z; v[7]=b.w;
}
__device__ __forceinline__ void storeRowB(__half* __restrict__ h,
                                          unsigned row, int sub, const float v[8]) {
    __half2 q0 = __floats2half2_rn(v[0], v[1]);
    __half2 q1 = __floats2half2_rn(v[2], v[3]);
    __half2 q2 = __floats2half2_rn(v[4], v[5]);
    __half2 q3 = __floats2half2_rn(v[6], v[7]);
    uint2 r0, r1;
    r0.x = *(unsigned*)&q0;  r0.y = *(unsigned*)&q1;   // cols 4*sub..+4
    r1.x = *(unsigned*)&q2;  r1.y = *(unsigned*)&q3;   // cols 32+4*sub..+4
    uint2* p = (uint2*)(h + (size_t)row * DD);
    p[sub]     = r0;
    p[sub + 8] = r1;
}

// --------------------------- SpMM kernel (fp16 src) -------------------------
// Four rows per warp, 8 lanes/row, lane owns 8 columns (mapping A).
// User rows (deg~5): 8 unrolled slots + scalar tail. Item rows (deg~10):
// 16 unrolled slots + scalar tail. Row type is warp-uniform.
template <typename DstT>
__global__ void __launch_bounds__(256, 6)
spmm_kernel(const __half* __restrict__ hsrc, DstT* __restrict__ hdst,
            const float* __restrict__ x, float fs) {
    const int lane = threadIdx.x & 31;
    const int sub  = lane & 7;
    const int team = lane >> 3;
    const int warp = blockIdx.x * (blockDim.x >> 5) + (threadIdx.x >> 5);
    const unsigned row = warp * 4 + team;   // exact tiling: never >= NN

    const int2 info = g_rowinfo[row];
    const int  st   = info.x;
    const int  len  = info.y;
    const float nv  = rsqrtf((float)(len + 1));

    float acc[8];
    #pragma unroll
    for (int k = 0; k < 8; k++) acc[k] = 0.f;

    if (row < NUSERS) {
        // ---- user rows: 8 unrolled slots ----
        const int n8 = (len < 8) ? len : 8;
        uint2 e0 = make_uint2(0u, 0u);
        if (sub < n8) e0 = g_edge[st + sub];
        #pragma unroll
        for (int j = 0; j < 8; j++) {
            unsigned sx = __shfl_sync(0xFFFFFFFFu, e0.x, j, 8);
            unsigned wb = __shfl_sync(0xFFFFFFFFu, e0.y, j, 8);
            if (j < n8) {
                float w = __uint_as_float(wb);
                float v[8];
                loadRow8(hsrc, sx, sub, v);
                #pragma unroll
                for (int k = 0; k < 8; k++) acc[k] = fmaf(w, v[k], acc[k]);
            }
        }
        for (int j = 8; j < len; j++) {               // deg > 8 tail (~7%)
            uint2 e2 = g_edge[st + j];
            float w = __uint_as_float(e2.y);
            float v[8];
            loadRow8(hsrc, e2.x, sub, v);
            #pragma unroll
            for (int k = 0; k < 8; k++) acc[k] = fmaf(w, v[k], acc[k]);
        }
    } else {
        // ---- item rows: 16 unrolled slots ----
        const int n16 = (len < 16) ? len : 16;
        uint2 e0 = make_uint2(0u, 0u);
        uint2 e1 = make_uint2(0u, 0u);
        if (sub < n16)     e0 = g_edge[st + sub];
        if (sub + 8 < n16) e1 = g_edge[st + sub + 8];
        #pragma unroll
        for (int j = 0; j < 16; j++) {
            unsigned sx = __shfl_sync(0xFFFFFFFFu, (j < 8) ? e0.x : e1.x, j & 7, 8);
            unsigned wb = __shfl_sync(0xFFFFFFFFu, (j < 8) ? e0.y : e1.y, j & 7, 8);
            if (j < n16) {
                float w = __uint_as_float(wb);
                float v[8];
                loadRow8(hsrc, sx, sub, v);
                #pragma unroll
                for (int k = 0; k < 8; k++) acc[k] = fmaf(w, v[k], acc[k]);
            }
        }
        for (int j = 16; j < len; j++) {              // deg > 16 tail (rare)
            uint2 e2 = g_edge[st + j];
            float w = __uint_as_float(e2.y);
            float v[8];
            loadRow8(hsrc, e2.x, sub, v);
            #pragma unroll
            for (int k = 0; k < 8; k++) acc[k] = fmaf(w, v[k], acc[k]);
        }
    }

    float sh[8], x0[8];
    loadRow8(hsrc, row, sub, sh);
    loadRow8(x,    row, sub, x0);

    const float cn = BETA_C * nv;
    const float cs = BETA_C * nv * nv;

    float r[8];
    #pragma unroll
    for (int k = 0; k < 8; k++)
        r[k] = fmaf(cn, acc[k], fmaf(cs, sh[k], ALPHA_C * x0[k])) * fs;

    storeRow8(hdst, row, sub, r);
}

// ------------------------ step-1 kernel (fp32 src = x) ----------------------
// Mapping B for coalesced fp32 gathers; anchor folded into self term.
// Same user/item slot split. storeRowB writes canonical layout.
__global__ void __launch_bounds__(256, 6)
spmm_step1_kernel(const float* __restrict__ x, __half* __restrict__ hdst) {
    const int lane = threadIdx.x & 31;
    const int sub  = lane & 7;
    const int team = lane >> 3;
    const int warp = blockIdx.x * (blockDim.x >> 5) + (threadIdx.x >> 5);
    const unsigned row = warp * 4 + team;

    const int2 info = g_rowinfo[row];
    const int  st   = info.x;
    const int  len  = info.y;
    const float nv  = rsqrtf((float)(len + 1));

    float acc[8];
    #pragma unroll
    for (int k = 0; k < 8; k++) acc[k] = 0.f;

    if (row < NUSERS) {
        const int n8 = (len < 8) ? len : 8;
        uint2 e0 = make_uint2(0u, 0u);
        if (sub < n8) e0 = g_edge[st + sub];
        #pragma unroll
        for (int j = 0; j < 8; j++) {
            unsigned sx = __shfl_sync(0xFFFFFFFFu, e0.x, j, 8);
            unsigned wb = __shfl_sync(0xFFFFFFFFu, e0.y, j, 8);
            if (j < n8) {
                float w = __uint_as_float(wb);
                float v[8];
                loadRowB(x, sx, sub, v);
                #pragma unroll
                for (int k = 0; k < 8; k++) acc[k] = fmaf(w, v[k], acc[k]);
            }
        }
        for (int j = 8; j < len; j++) {
            uint2 e2 = g_edge[st + j];
            float w = __uint_as_float(e2.y);
            float v[8];
            loadRowB(x, e2.x, sub, v);
            #pragma unroll
            for (int k = 0; k < 8; k++) acc[k] = fmaf(w, v[k], acc[k]);
        }
    } else {
        const int n16 = (len < 16) ? len : 16;
        uint2 e0 = make_uint2(0u, 0u);
        uint2 e1 = make_uint2(0u, 0u);
        if (sub < n16)     e0 = g_edge[st + sub];
        if (sub + 8 < n16) e1 = g_edge[st + sub + 8];
        #pragma unroll
        for (int j = 0; j < 16; j++) {
            unsigned sx = __shfl_sync(0xFFFFFFFFu, (j < 8) ? e0.x : e1.x, j & 7, 8);
            unsigned wb = __shfl_sync(0xFFFFFFFFu, (j < 8) ? e0.y : e1.y, j & 7, 8);
            if (j < n16) {
                float w = __uint_as_float(wb);
                float v[8];
                loadRowB(x, sx, sub, v);
                #pragma unroll
                for (int k = 0; k < 8; k++) acc[k] = fmaf(w, v[k], acc[k]);
            }
        }
        for (int j = 16; j < len; j++) {
            uint2 e2 = g_edge[st + j];
            float w = __uint_as_float(e2.y);
            float v[8];
            loadRowB(x, e2.x, sub, v);
            #pragma unroll
            for (int k = 0; k < 8; k++) acc[k] = fmaf(w, v[k], acc[k]);
        }
    }

    float sh[8];
    loadRowB(x, row, sub, sh);

    const float cn = BETA_C * nv;
    const float ca = BETA_C * nv * nv + ALPHA_C;    // folded self + anchor

    float r[8];
    #pragma unroll
    for (int k = 0; k < 8; k++)
        r[k] = fmaf(cn, acc[k], ca * sh[k]);

    storeRowB(hdst, row, sub, r);
}

// --------------------------------- launch ----------------------------------
extern "C" void kernel_launch(void* const* d_in, const int* in_sizes, int n_in,
                              void* d_out, int out_size) {
    const float* x    = (const float*)d_in[0];
    const int*   uidx = (const int*)  d_in[1];
    const int*   iidx = (const int*)  d_in[2];
    float*       out  = (float*)d_out;

    const int T = 256;

    void* p_cnt   = nullptr; cudaGetSymbolAddress(&p_cnt,   g_cnt);
    void* p_alloc = nullptr; cudaGetSymbolAddress(&p_alloc, g_alloc);
    void* p_hh    = nullptr; cudaGetSymbolAddress(&p_hh,    g_hh);
    __half* h0 = (__half*)p_hh;
    __half* h1 = h0 + (size_t)NN * DD;

    // ---- CSR build ----
    cudaMemsetAsync(p_cnt,   0, sizeof(int) * NN);
    cudaMemsetAsync(p_alloc, 0, sizeof(int));
    count_kernel<<<(NE + T - 1) / T, T>>>(uidx, iidx);
    alloc_kernel<<<(NN + T - 1) / T, T>>>();
    fill_kernel <<<(NE + T - 1) / T, T>>>(uidx, iidx);

    // ---- K = 4 diffusion steps ----
    const int rows_per_blk = (T / 32) * 4;            // 32 rows / block
    const int spmm_blocks  = (NN + rows_per_blk - 1) / rows_per_blk;

    spmm_step1_kernel<<<spmm_blocks, T>>>(x, h0);
    spmm_kernel<__half><<<spmm_blocks, T>>>(h0, h1, x, 1.0f);
    spmm_kernel<__half><<<spmm_blocks, T>>>(h1, h0, x, 1.0f);
    spmm_kernel<float ><<<spmm_blocks, T>>>(h0, out, x, INV_GAMMA);
}

// round 11
// speedup vs baseline: 1.0635x; 1.0555x over previous
#include <cuda_runtime.h>
#include <cuda_fp16.h>
#include <cstdint>

// ---------------------------------------------------------------------------
// MGDCF diffusion: h_{t+1} = BETA * A_norm h_t + ALPHA * h0, K=4 steps.
// Round 10: unbundled from R9 —
//   * fp16-source spmm_kernel: R9 version (degree-matched 8/16-slot paths,
//     __launch_bounds__(256,6)) — the credited improvement.
//   * spmm_step1_kernel: reverted to the R8 version exactly (no row-type
//     branch, plain launch bounds) which measured 66.9us.
// ---------------------------------------------------------------------------

#define NUSERS 200000
#define NITEMS 100000
#define NN     300000              // total nodes (div by 4 -> exact tiling)
#define NE     1000000             // user-item pairs
#define DD     64                  // feature dim

static constexpr float ALPHA_C = 0.1f;
static constexpr float BETA_C  = 0.9f;
static constexpr double GAMMA_D =
    (0.9 * 0.9 * 0.9 * 0.9) + 0.1 * (1.0 + 0.9 + 0.81 + 0.729);   // = 1.0
static constexpr float INV_GAMMA = (float)(1.0 / GAMMA_D);

// ------------------------- device scratch (static) -------------------------
__device__ __half g_hh[2][(size_t)NN * DD];  // ping-pong fp16 h buffers (76.8 MB)
__device__ int    g_cnt[NN];                 // real in-degree (excl. self loop)
__device__ float  g_norm[NN];                // (deg incl. self)^-1/2
__device__ int2   g_rowinfo[NN];             // (segment start, real in-degree)
__device__ int    g_cursor[NN];              // fill cursors
__device__ uint2  g_edge[2 * NE];            // (src, norm[src] bits), 16 MB
__device__ int    g_alloc;                   // global segment allocator

// ------------------------------ build kernels ------------------------------

__global__ void count_kernel(const int* __restrict__ uidx,
                             const int* __restrict__ iidx) {
    int e = blockIdx.x * blockDim.x + threadIdx.x;
    if (e >= NE) return;
    int u  = uidx[e];
    int it = iidx[e] + NUSERS;
    atomicAdd(&g_cnt[u], 1);
    atomicAdd(&g_cnt[it], 1);
}

__global__ void alloc_kernel() {
    int v    = blockIdx.x * blockDim.x + threadIdx.x;
    int lane = threadIdx.x & 31;
    int c = 0;
    if (v < NN) {
        c = g_cnt[v];
        g_norm[v] = rsqrtf((float)(c + 1));
    }
    int inc = c;
    #pragma unroll
    for (int o = 1; o < 32; o <<= 1) {
        int t = __shfl_up_sync(0xFFFFFFFFu, inc, o);
        if (lane >= o) inc += t;
    }
    int total = __shfl_sync(0xFFFFFFFFu, inc, 31);
    int base = 0;
    if (lane == 31) base = atomicAdd(&g_alloc, total);
    base = __shfl_sync(0xFFFFFFFFu, base, 31);
    if (v < NN) {
        int st = base + inc - c;
        g_rowinfo[v] = make_int2(st, c);
        g_cursor[v]  = st;
    }
}

__global__ void fill_kernel(const int* __restrict__ uidx,
                            const int* __restrict__ iidx) {
    int e = blockIdx.x * blockDim.x + threadIdx.x;
    if (e >= NE) return;
    int u  = uidx[e];
    int it = iidx[e] + NUSERS;
    float nu = g_norm[u];
    float ni = g_norm[it];
    int p0 = atomicAdd(&g_cursor[it], 1);
    g_edge[p0] = make_uint2((unsigned)u, __float_as_uint(nu));
    int p1 = atomicAdd(&g_cursor[u], 1);
    g_edge[p1] = make_uint2((unsigned)it, __float_as_uint(ni));
}

// ----------------------- 8-wide row load/store helpers ----------------------
// Mapping A (fp16 rows): lane `sub` owns columns [sub*8, sub*8+8).

__device__ __forceinline__ void loadRow8(const float* __restrict__ h,
                                         unsigned row, int sub, float v[8]) {
    const float4* p = (const float4*)(h + (size_t)row * DD) + sub * 2;
    float4 a = p[0];
    float4 b = p[1];
    v[0]=a.x; v[1]=a.y; v[2]=a.z; v[3]=a.w;
    v[4]=b.x; v[5]=b.y; v[6]=b.z; v[7]=b.w;
}
__device__ __forceinline__ void loadRow8(const __half* __restrict__ h,
                                         unsigned row, int sub, float v[8]) {
    uint4 r = ((const uint4*)(h + (size_t)row * DD))[sub];
    float2 f0 = __half22float2(*(__half2*)&r.x);
    float2 f1 = __half22float2(*(__half2*)&r.y);
    float2 f2 = __half22float2(*(__half2*)&r.z);
    float2 f3 = __half22float2(*(__half2*)&r.w);
    v[0]=f0.x; v[1]=f0.y; v[2]=f1.x; v[3]=f1.y;
    v[4]=f2.x; v[5]=f2.y; v[6]=f3.x; v[7]=f3.y;
}
__device__ __forceinline__ void storeRow8(float* __restrict__ h,
                                          unsigned row, int sub, const float v[8]) {
    float4* p = (float4*)(h + (size_t)row * DD) + sub * 2;
    p[0] = make_float4(v[0], v[1], v[2], v[3]);
    p[1] = make_float4(v[4], v[5], v[6], v[7]);
}
__device__ __forceinline__ void storeRow8(__half* __restrict__ h,
                                          unsigned row, int sub, const float v[8]) {
    __half2 h0 = __floats2half2_rn(v[0], v[1]);
    __half2 h1 = __floats2half2_rn(v[2], v[3]);
    __half2 h2 = __floats2half2_rn(v[4], v[5]);
    __half2 h3 = __floats2half2_rn(v[6], v[7]);
    uint4 r;
    r.x = *(unsigned*)&h0;  r.y = *(unsigned*)&h1;
    r.z = *(unsigned*)&h2;  r.w = *(unsigned*)&h3;
    ((uint4*)(h + (size_t)row * DD))[sub] = r;
}

// Mapping B (fp32 rows, coalesced): lane `sub` owns columns
// {4*sub..+4} and {32+4*sub..+4}; loads are p[sub], p[sub+8] (128B coalesced).
__device__ __forceinline__ void loadRowB(const float* __restrict__ h,
                                         unsigned row, int sub, float v[8]) {
    const float4* p = (const float4*)(h + (size_t)row * DD);
    float4 a = p[sub];
    float4 b = p[sub + 8];
    v[0]=a.x; v[1]=a.y; v[2]=a.z; v[3]=a.w;
    v[4]=b.x; v[5]=b.y; v[6]=b.z; v[7]=b.w;
}
__device__ __forceinline__ void storeRowB(__half* __restrict__ h,
                                          unsigned row, int sub, const float v[8]) {
    __half2 q0 = __floats2half2_rn(v[0], v[1]);
    __half2 q1 = __floats2half2_rn(v[2], v[3]);
    __half2 q2 = __floats2half2_rn(v[4], v[5]);
    __half2 q3 = __floats2half2_rn(v[6], v[7]);
    uint2 r0, r1;
    r0.x = *(unsigned*)&q0;  r0.y = *(unsigned*)&q1;   // cols 4*sub..+4
    r1.x = *(unsigned*)&q2;  r1.y = *(unsigned*)&q3;   // cols 32+4*sub..+4
    uint2* p = (uint2*)(h + (size_t)row * DD);
    p[sub]     = r0;
    p[sub + 8] = r1;
}

// --------------------------- SpMM kernel (fp16 src) -------------------------
// R9 version: four rows per warp, 8 lanes/row, mapping A. User rows (deg~5):
// 8 unrolled slots; item rows (deg~10): 16 unrolled slots; scalar tails.
template <typename DstT>
__global__ void __launch_bounds__(256, 6)
spmm_kernel(const __half* __restrict__ hsrc, DstT* __restrict__ hdst,
            const float* __restrict__ x, float fs) {
    const int lane = threadIdx.x & 31;
    const int sub  = lane & 7;
    const int team = lane >> 3;
    const int warp = blockIdx.x * (blockDim.x >> 5) + (threadIdx.x >> 5);
    const unsigned row = warp * 4 + team;   // exact tiling: never >= NN

    const int2 info = g_rowinfo[row];
    const int  st   = info.x;
    const int  len  = info.y;
    const float nv  = rsqrtf((float)(len + 1));

    float acc[8];
    #pragma unroll
    for (int k = 0; k < 8; k++) acc[k] = 0.f;

    if (row < NUSERS) {
        // ---- user rows: 8 unrolled slots ----
        const int n8 = (len < 8) ? len : 8;
        uint2 e0 = make_uint2(0u, 0u);
        if (sub < n8) e0 = g_edge[st + sub];
        #pragma unroll
        for (int j = 0; j < 8; j++) {
            unsigned sx = __shfl_sync(0xFFFFFFFFu, e0.x, j, 8);
            unsigned wb = __shfl_sync(0xFFFFFFFFu, e0.y, j, 8);
            if (j < n8) {
                float w = __uint_as_float(wb);
                float v[8];
                loadRow8(hsrc, sx, sub, v);
                #pragma unroll
                for (int k = 0; k < 8; k++) acc[k] = fmaf(w, v[k], acc[k]);
            }
        }
        for (int j = 8; j < len; j++) {               // deg > 8 tail (~7%)
            uint2 e2 = g_edge[st + j];
            float w = __uint_as_float(e2.y);
            float v[8];
            loadRow8(hsrc, e2.x, sub, v);
            #pragma unroll
            for (int k = 0; k < 8; k++) acc[k] = fmaf(w, v[k], acc[k]);
        }
    } else {
        // ---- item rows: 16 unrolled slots ----
        const int n16 = (len < 16) ? len : 16;
        uint2 e0 = make_uint2(0u, 0u);
        uint2 e1 = make_uint2(0u, 0u);
        if (sub < n16)     e0 = g_edge[st + sub];
        if (sub + 8 < n16) e1 = g_edge[st + sub + 8];
        #pragma unroll
        for (int j = 0; j < 16; j++) {
            unsigned sx = __shfl_sync(0xFFFFFFFFu, (j < 8) ? e0.x : e1.x, j & 7, 8);
            unsigned wb = __shfl_sync(0xFFFFFFFFu, (j < 8) ? e0.y : e1.y, j & 7, 8);
            if (j < n16) {
                float w = __uint_as_float(wb);
                float v[8];
                loadRow8(hsrc, sx, sub, v);
                #pragma unroll
                for (int k = 0; k < 8; k++) acc[k] = fmaf(w, v[k], acc[k]);
            }
        }
        for (int j = 16; j < len; j++) {              // deg > 16 tail (rare)
            uint2 e2 = g_edge[st + j];
            float w = __uint_as_float(e2.y);
            float v[8];
            loadRow8(hsrc, e2.x, sub, v);
            #pragma unroll
            for (int k = 0; k < 8; k++) acc[k] = fmaf(w, v[k], acc[k]);
        }
    }

    float sh[8], x0[8];
    loadRow8(hsrc, row, sub, sh);
    loadRow8(x,    row, sub, x0);

    const float cn = BETA_C * nv;
    const float cs = BETA_C * nv * nv;

    float r[8];
    #pragma unroll
    for (int k = 0; k < 8; k++)
        r[k] = fmaf(cn, acc[k], fmaf(cs, sh[k], ALPHA_C * x0[k])) * fs;

    storeRow8(hdst, row, sub, r);
}

// ------------------------ step-1 kernel (fp32 src = x) ----------------------
// R8 version exactly: no row-type branch, single 16-slot unrolled loop,
// mapping B coalesced gathers, folded self+anchor, plain launch bounds.
__global__ void __launch_bounds__(256)
spmm_step1_kernel(const float* __restrict__ x, __half* __restrict__ hdst) {
    const int lane = threadIdx.x & 31;
    const int sub  = lane & 7;
    const int team = lane >> 3;
    const int warp = blockIdx.x * (blockDim.x >> 5) + (threadIdx.x >> 5);
    const unsigned row = warp * 4 + team;

    const int2 info = g_rowinfo[row];
    const int  st   = info.x;
    const int  len  = info.y;
    const float nv  = rsqrtf((float)(len + 1));

    float acc[8];
    #pragma unroll
    for (int k = 0; k < 8; k++) acc[k] = 0.f;

    const int n16 = (len < 16) ? len : 16;
    uint2 e0 = make_uint2(0u, 0u);
    uint2 e1 = make_uint2(0u, 0u);
    if (sub < n16)     e0 = g_edge[st + sub];
    if (sub + 8 < n16) e1 = g_edge[st + sub + 8];

    #pragma unroll
    for (int j = 0; j < 16; j++) {
        unsigned sx = __shfl_sync(0xFFFFFFFFu, (j < 8) ? e0.x : e1.x, j & 7, 8);
        unsigned wb = __shfl_sync(0xFFFFFFFFu, (j < 8) ? e0.y : e1.y, j & 7, 8);
        if (j < n16) {
            float w = __uint_as_float(wb);
            float v[8];
            loadRowB(x, sx, sub, v);
            #pragma unroll
            for (int k = 0; k < 8; k++) acc[k] = fmaf(w, v[k], acc[k]);
        }
    }

    for (int j = 16; j < len; j++) {
        uint2 e2 = g_edge[st + j];
        float w = __uint_as_float(e2.y);
        float v[8];
        loadRowB(x, e2.x, sub, v);
        #pragma unroll
        for (int k = 0; k < 8; k++) acc[k] = fmaf(w, v[k], acc[k]);
    }

    float sh[8];
    loadRowB(x, row, sub, sh);

    const float cn = BETA_C * nv;
    const float ca = BETA_C * nv * nv + ALPHA_C;    // folded self + anchor

    float r[8];
    #pragma unroll
    for (int k = 0; k < 8; k++)
        r[k] = fmaf(cn, acc[k], ca * sh[k]);

    storeRowB(hdst, row, sub, r);
}

// --------------------------------- launch ----------------------------------
extern "C" void kernel_launch(void* const* d_in, const int* in_sizes, int n_in,
                              void* d_out, int out_size) {
    const float* x    = (const float*)d_in[0];
    const int*   uidx = (const int*)  d_in[1];
    const int*   iidx = (const int*)  d_in[2];
    float*       out  = (float*)d_out;

    const int T = 256;

    void* p_cnt   = nullptr; cudaGetSymbolAddress(&p_cnt,   g_cnt);
    void* p_alloc = nullptr; cudaGetSymbolAddress(&p_alloc, g_alloc);
    void* p_hh    = nullptr; cudaGetSymbolAddress(&p_hh,    g_hh);
    __half* h0 = (__half*)p_hh;
    __half* h1 = h0 + (size_t)NN * DD;

    // ---- CSR build ----
    cudaMemsetAsync(p_cnt,   0, sizeof(int) * NN);
    cudaMemsetAsync(p_alloc, 0, sizeof(int));
    count_kernel<<<(NE + T - 1) / T, T>>>(uidx, iidx);
    alloc_kernel<<<(NN + T - 1) / T, T>>>();
    fill_kernel <<<(NE + T - 1) / T, T>>>(uidx, iidx);

    // ---- K = 4 diffusion steps ----
    const int rows_per_blk = (T / 32) * 4;            // 32 rows / block
    const int spmm_blocks  = (NN + rows_per_blk - 1) / rows_per_blk;

    spmm_step1_kernel<<<spmm_blocks, T>>>(x, h0);
    spmm_kernel<__half><<<spmm_blocks, T>>>(h0, h1, x, 1.0f);
    spmm_kernel<__half><<<spmm_blocks, T>>>(h1, h0, x, 1.0f);
    spmm_kernel<float ><<<spmm_blocks, T>>>(h0, out, x, INV_GAMMA);
}